// round 15
// baseline (speedup 1.0000x reference)
#include <cuda_runtime.h>
#include <math.h>

#define BB 32
#define TT 256
#define EE 256
#define HH 512
#define G4 2048   // 4*HH
#define KK 20
#define START_TAG 18
#define END_TAG 19
#define NEGV (-10000.0f)
#define NBLK 128

// ---------------- device-global scratch ----------------
__device__ float g_pre[(size_t)2 * TT * G4 * BB];              // [dir][t][gate][b]
__device__ __align__(16) float2 g_hp[2][2][256 * BB];          // [dir][buf][pair*BB+b]
__device__ float g_lo2[(size_t)2 * TT * HH * BB];              // [dir][t][j][b]
__device__ float g_feats[(size_t)BB * TT * KK];                // [b][t][k]
__device__ __align__(16) unsigned g_flag[2][2][64];            // [dir][k-half][block] step flags

// ---------------- helpers ----------------
__device__ __forceinline__ unsigned smem_u32(const void* p) {
    unsigned a;
    asm("{ .reg .u64 t; cvta.to.shared.u64 t, %1; cvt.u32.u64 %0, t; }" : "=r"(a) : "l"(p));
    return a;
}
__device__ __forceinline__ void fma2(unsigned long long& acc, unsigned long long a, unsigned long long b) {
    asm("fma.rn.f32x2 %0, %1, %2, %0;" : "+l"(acc) : "l"(a), "l"(b));
}
__device__ __forceinline__ void lds_v2u64(unsigned addr, unsigned long long& a, unsigned long long& b) {
    asm("ld.shared.v2.u64 {%0,%1}, [%2];" : "=l"(a), "=l"(b) : "r"(addr));
}
__device__ __forceinline__ unsigned long long lds_u64(unsigned addr) {
    unsigned long long v;
    asm("ld.shared.u64 %0, [%1];" : "=l"(v) : "r"(addr));
    return v;
}
__device__ __forceinline__ float hsum2(unsigned long long a) {
    return __uint_as_float((unsigned)a) + __uint_as_float((unsigned)(a >> 32));
}
__device__ __forceinline__ void named_bar(int id) {
    asm volatile("bar.sync %0, 128;" :: "r"(id) : "memory");
}
__device__ __forceinline__ void mbar_wait(unsigned addr, unsigned parity) {
    unsigned done;
    do {
        asm volatile(
            "{ .reg .pred p;\n\t"
            "mbarrier.try_wait.parity.acquire.cta.shared::cta.b64 p, [%1], %2, 0x989680;\n\t"
            "selp.b32 %0, 1, 0, p; }"
            : "=r"(done) : "r"(addr), "r"(parity) : "memory");
    } while (!done);
}
__device__ __forceinline__ unsigned ld_acq(const unsigned* p) {
    unsigned r;
    asm volatile("ld.acquire.gpu.global.u32 %0, [%1];" : "=r"(r) : "l"(p) : "memory");
    return r;
}

// ---------------- init: reset barrier state (inside graph, every replay) ----------------
__global__ void k_init() {
    int i = blockIdx.x * blockDim.x + threadIdx.x;
    if (i < 2 * 2 * 64) ((unsigned*)g_flag)[i] = 0u;
}

// no-op: launch-order shim so ncu's -s 5 window lands on k_lstm
__global__ void k_nop() {}

// ---------------- input-projection GEMM (f32x2), embedding gather fused ----------------
__global__ void __launch_bounds__(256) k_pregemm(
    const int* __restrict__ sent, const float* __restrict__ emb,
    const float* __restrict__ Wf, const float* __restrict__ Wb,
    const float* __restrict__ bf, const float* __restrict__ bb)
{
    extern __shared__ float sm[];
    float* xsf = sm;               // x pairs: [ep][b][2], stride 68 floats/ep
    float* wsf = sm + 128 * 68;    // w rows:  [r][e], stride 258 floats/row
    __shared__ int stok[BB];

    int t = blockIdx.x, gc = blockIdx.y, dir = blockIdx.z;
    int tid = threadIdx.x;
    if (tid < BB) stok[tid] = sent[tid * TT + t];
    __syncthreads();

    const float* W  = dir ? Wb : Wf;
    const float* bi = dir ? bb : bf;

    for (int i = tid; i < BB * EE; i += 256) {
        int b = i >> 8, e = i & 255;
        xsf[(e >> 1) * 68 + b * 2 + (e & 1)] = emb[(size_t)stok[b] * EE + e];
    }
    int g0blk = gc * 64;
    for (int i = tid; i < 64 * EE; i += 256) {
        int r = i >> 8, e = i & 255;
        wsf[r * 258 + e] = W[(size_t)(g0blk + r) * EE + e];
    }
    __syncthreads();

    int tx = tid & 15, ty = tid >> 4;
    int b0 = tx * 2;
    int g0 = ty * 4;
    unsigned xb = smem_u32(xsf) + (unsigned)b0 * 8u;
    unsigned wb = smem_u32(wsf) + (unsigned)g0 * 1032u;

    unsigned long long a[4][2];
#pragma unroll
    for (int q = 0; q < 4; q++) { a[q][0] = 0ull; a[q][1] = 0ull; }

#pragma unroll 4
    for (int ep = 0; ep < 128; ep++) {
        unsigned long long x0, x1;
        lds_v2u64(xb + (unsigned)ep * 272u, x0, x1);
        unsigned long long w0 = lds_u64(wb + (unsigned)ep * 8u);
        unsigned long long w1 = lds_u64(wb + 1032u + (unsigned)ep * 8u);
        unsigned long long w2 = lds_u64(wb + 2064u + (unsigned)ep * 8u);
        unsigned long long w3 = lds_u64(wb + 3096u + (unsigned)ep * 8u);
        fma2(a[0][0], w0, x0); fma2(a[0][1], w0, x1);
        fma2(a[1][0], w1, x0); fma2(a[1][1], w1, x1);
        fma2(a[2][0], w2, x0); fma2(a[2][1], w2, x1);
        fma2(a[3][0], w3, x0); fma2(a[3][1], w3, x1);
    }

    size_t base = (((size_t)dir * TT + t) * G4 + g0blk) * BB;
#pragma unroll
    for (int q = 0; q < 4; q++) {
        int g = g0 + q;
        float bv = bi[g0blk + g];
        float2 st = make_float2(hsum2(a[q][0]) + bv, hsum2(a[q][1]) + bv);
        *(float2*)&g_pre[base + (size_t)g * BB + b0] = st;
    }
}

// ---------------- persistent BiLSTM recurrence (R13 body, flag-array barrier) ----------------
// 128 blocks x 256 threads. warp w: dir=w>>2, p=(w>>1)&1 (j-pair), kh=w&1 (k-half).
// h exchange split per k-half (half hf produced by blocks jgrp in [64hf,64hf+64)).
// Arrive: per-block flag (st.release.gpu, distinct addresses -> no atomic serialization).
// Poller WARP (q<2) scans 64 flags (2 aligned acquire loads/lane) + reduce_min, then
// lane 0 TMAs 32KB into smem + own mbarrier. MAC warp kh waits only mbar[dir][kh].
__global__ void __launch_bounds__(256, 1) k_lstm(
    const float* __restrict__ Wfhh, const float* __restrict__ Wbhh,
    const float* __restrict__ bfhh, const float* __restrict__ bbhh,
    const int* __restrict__ lengths)
{
    extern __shared__ float sm[];
    // floats: [0,16384) interleaved weights; [16384,49152) h; [49152,50176) partials;
    // bytes 200704..200736: four mbarriers [dir][half]
    const int jgrp = (int)blockIdx.x;
    const int tid = threadIdx.x;
    const int w = tid >> 5, lane = tid & 31;
    const int dir = w >> 2, p = (w >> 1) & 1, kh = w & 1;
    const int q = w - dir * 4;                 // warp index within half, 0..3
    const int jown = jgrp * 4 + p * 2 + kh;
    const unsigned mbase = smem_u32(sm) + 200704u;

    // one-time: interleaved weight load
    for (int idx = tid; idx < 16384; idx += 256) {
        int ww = idx >> 11;
        int r = idx & 2047;
        int kq = r >> 4, c = r & 15;
        int jj = c >> 3, gate = (c >> 1) & 3, kk = c & 1;
        int d = ww >> 2, pp = (ww >> 1) & 1, kk2 = ww & 1;
        const float* W = d ? Wbhh : Wfhh;
        int jr = jgrp * 4 + pp * 2 + jj;
        int k = kk2 * 256 + kq * 2 + kk;
        sm[idx] = W[((size_t)(gate * HH + jr)) * HH + k];
    }
    for (int i = tid; i < 2 * HH * BB; i += 256) sm[16384 + i] = 0.0f;
    if (tid == 0) {
#pragma unroll
        for (int c = 0; c < 4; c++)
            asm volatile("mbarrier.init.shared.b64 [%0], 1;" :: "r"(mbase + (unsigned)c * 8u) : "memory");
    }
    __syncthreads();

    const float* bhh = dir ? bbhh : bfhh;
    float bg[4];
#pragma unroll
    for (int g = 0; g < 4; g++) bg[g] = bhh[g * HH + jown];
    const int mylen = lengths[lane];

    const unsigned smWb = smem_u32(sm) + (unsigned)w * 8192u;
    const unsigned smh  = smem_u32(sm) + 65536u + (unsigned)dir * 65536u + (unsigned)kh * 32768u + (unsigned)lane * 8u;
    const unsigned hdst = smem_u32(sm) + 65536u + (unsigned)dir * 65536u;
    const unsigned mb_own = mbase + (unsigned)(dir * 2 + kh) * 8u;
    float* part = sm + 49152;
    const int barid = 1 + dir;
    const bool is_pollwarp = (q < 2);           // warp q polls half hf=q for its dir

    // prefetch pre-gates for t=0
    float cz[4];
    int cpos = (dir && 0 < mylen) ? (mylen - 1) : 0;
    {
        size_t pb = (((size_t)dir * TT + cpos) * G4) * BB + lane;
#pragma unroll
        for (int g = 0; g < 4; g++) cz[g] = __ldcs(&g_pre[pb + (size_t)(g * HH + jown) * BB]);
    }

    float c = 0.0f;
    for (int t = 0; t < TT; t++) {
        // prefetch next-step pre-gates (independent of barrier / h)
        float nz[4] = {0.f, 0.f, 0.f, 0.f};
        int npos = 0;
        if (t + 1 < TT) {
            npos = t + 1;
            if (dir && (t + 1) < mylen) npos = mylen - 1 - (t + 1);
            size_t pb = (((size_t)dir * TT + npos) * G4) * BB + lane;
#pragma unroll
            for (int g = 0; g < 4; g++) nz[g] = __ldcs(&g_pre[pb + (size_t)(g * HH + jown) * BB]);
        }

        if (t) {
            // poller warps: scan this half's 64 flags in parallel, then lane 0 TMAs 32KB
            if (is_pollwarp) {
                const int hf = q;    // 0 or 1
                const unsigned* fl = &g_flag[dir][hf][0];
                unsigned need = (unsigned)t;
                for (;;) {
                    unsigned m0 = ld_acq(fl + lane);
                    unsigned m1 = ld_acq(fl + 32 + lane);
                    unsigned m = __reduce_min_sync(0xffffffffu, min(m0, m1));
                    if (m >= need) break;
                    __nanosleep(64);
                }
                if (lane == 0) {
                    unsigned mb = mbase + (unsigned)(dir * 2 + hf) * 8u;
                    asm volatile("fence.proxy.async;" ::: "memory");
                    asm volatile("mbarrier.arrive.expect_tx.shared.b64 _, [%0], %1;"
                                 :: "r"(mb), "r"(32768u) : "memory");
                    asm volatile("cp.async.bulk.shared::cluster.global.mbarrier::complete_tx::bytes [%0], [%1], %2, [%3];"
                                 :: "r"(hdst + (unsigned)hf * 32768u),
                                    "l"((const char*)&g_hp[dir][t & 1][0] + (size_t)hf * 32768),
                                    "r"(32768u), "r"(mb)
                                 : "memory");
                }
            }
            // each MAC warp waits only the half it reads
            mbar_wait(mb_own, (unsigned)((t - 1) & 1));
        }

        // ---- MAC over this warp's k-half for both j's of the pair ----
        unsigned long long ai0 = 0, af0 = 0, ag0 = 0, ao0 = 0;
        unsigned long long ai1 = 0, af1 = 0, ag1 = 0, ao1 = 0;
#pragma unroll 4
        for (int kq = 0; kq < 128; kq++) {
            unsigned wa = smWb + (unsigned)kq * 64u;
            unsigned long long wi0, wf0, wg0, wo0, wi1, wf1, wg1, wo1;
            lds_v2u64(wa,       wi0, wf0);
            lds_v2u64(wa + 16u, wg0, wo0);
            lds_v2u64(wa + 32u, wi1, wf1);
            lds_v2u64(wa + 48u, wg1, wo1);
            unsigned long long h2 = lds_u64(smh + (unsigned)kq * 256u);
            fma2(ai0, wi0, h2); fma2(af0, wf0, h2); fma2(ag0, wg0, h2); fma2(ao0, wo0, h2);
            fma2(ai1, wi1, h2); fma2(af1, wf1, h2); fma2(ag1, wg1, h2); fma2(ao1, wo1, h2);
        }

        // partner partials: the j this warp does NOT own (jj = 1-kh)
        float po[4], pn[4];
        if (kh == 0) { pn[0] = hsum2(ai1); pn[1] = hsum2(af1); pn[2] = hsum2(ag1); pn[3] = hsum2(ao1);
                       po[0] = hsum2(ai0); po[1] = hsum2(af0); po[2] = hsum2(ag0); po[3] = hsum2(ao0); }
        else         { pn[0] = hsum2(ai0); pn[1] = hsum2(af0); pn[2] = hsum2(ag0); pn[3] = hsum2(ao0);
                       po[0] = hsum2(ai1); po[1] = hsum2(af1); po[2] = hsum2(ag1); po[3] = hsum2(ao1); }
#pragma unroll
        for (int g = 0; g < 4; g++) part[(w * 4 + g) * 32 + lane] = pn[g];
        named_bar(barid);

        float z[4];
#pragma unroll
        for (int g = 0; g < 4; g++)
            z[g] = cz[g] + bg[g] + po[g] + part[((w ^ 1) * 4 + g) * 32 + lane];

        float gi = 1.0f / (1.0f + expf(-z[0]));
        float gf = 1.0f / (1.0f + expf(-z[1]));
        float gg = 1.0f - 2.0f / (expf(2.0f * z[2]) + 1.0f);
        float go = 1.0f / (1.0f + expf(-z[3]));

        c = gf * c + gi * gg;
        float h = go * (1.0f - 2.0f / (expf(2.0f * c) + 1.0f));

        int pairIdx = jgrp * 2 + p;
        ((float*)&g_hp[dir][(t + 1) & 1][pairIdx * BB])[lane * 2 + kh] = h;
        g_lo2[(((size_t)dir * TT + cpos) * HH + jown) * BB + lane] = h;

        if (t + 1 < TT) {
            named_bar(barid);   // all 4 warps of this half stored h (and done reading smem h)
            if (tid == dir * 128) {
                asm volatile("st.release.gpu.global.u32 [%0], %1;"
                             :: "l"(&g_flag[dir][jgrp >> 6][jgrp & 63]), "r"((unsigned)(t + 1)) : "memory");
            }
        }
#pragma unroll
        for (int g = 0; g < 4; g++) cz[g] = nz[g];
        cpos = npos;
    }
}

// ---------------- feats: per-t GEMM, 4 timesteps per block (Wout staged once) ----------------
__global__ void __launch_bounds__(640) k_feats(
    const float* __restrict__ Wout, const float* __restrict__ bout)
{
    extern __shared__ float sm[];
    float* sW = sm;                 // [20][1024]
    float* sh = sm + 20480;         // [1024][32]
    __shared__ float sb[KK];
    int tid = threadIdx.x, warp = tid >> 5, lane = tid & 31;

    for (int i = tid * 4; i < KK * 2 * HH; i += 2560)
        *(float4*)&sW[i] = *(const float4*)&Wout[i];
    if (tid < KK) sb[tid] = bout[tid];

    for (int tt = 0; tt < 4; tt++) {
        int t = blockIdx.x * 4 + tt;
        for (int d = 0; d < 2; d++) {
            const float4* src = (const float4*)&g_lo2[(((size_t)d * TT + t) * HH) * BB];
            float4* dst = (float4*)&sh[d * HH * BB];
            for (int i = tid; i < HH * BB / 4; i += 640) dst[i] = src[i];
        }
        __syncthreads();

        float acc = 0.0f;
        const float* wrow = &sW[warp * 2 * HH];
#pragma unroll 8
        for (int jj = 0; jj < 2 * HH; jj += 4) {
            float4 wv = *(const float4*)&wrow[jj];
            acc = fmaf(wv.x, sh[(jj + 0) * BB + lane], acc);
            acc = fmaf(wv.y, sh[(jj + 1) * BB + lane], acc);
            acc = fmaf(wv.z, sh[(jj + 2) * BB + lane], acc);
            acc = fmaf(wv.w, sh[(jj + 3) * BB + lane], acc);
        }
        g_feats[((size_t)lane * TT + t) * KK + warp] = acc + sb[warp];
        __syncthreads();
    }
}

// ---------------- Viterbi forward + backtrace, one warp per batch ----------------
__global__ void k_viterbi(const float* __restrict__ trans,
                          const int* __restrict__ lengths,
                          float* __restrict__ out)
{
    __shared__ unsigned char bp[TT][KK];
    int b = blockIdx.x;
    int nx = threadIdx.x;
    int len = lengths[b];

    float tr[KK];
#pragma unroll
    for (int p = 0; p < KK; p++) tr[p] = (nx < KK) ? trans[nx * KK + p] : 0.0f;

    float fv = (nx == START_TAG) ? 0.0f : NEGV;
    for (int t = 0; t < len; t++) {
        float best = -INFINITY; int barg = 0;
#pragma unroll
        for (int p = 0; p < KK; p++) {
            float fvp = __shfl_sync(0xffffffffu, fv, p);
            float s = fvp + tr[p];
            if (s > best) { best = s; barg = p; }
        }
        if (nx < KK) {
            bp[t][nx] = (unsigned char)barg;
            fv = best + g_feats[((size_t)b * TT + t) * KK + nx];
        } else {
            fv = NEGV;
        }
        __syncwarp();
    }

    float term = (nx < KK) ? (fv + trans[END_TAG * KK + nx]) : -INFINITY;
    float bestv = -INFINITY; int bt = 0;
#pragma unroll
    for (int p = 0; p < KK; p++) {
        float v = __shfl_sync(0xffffffffu, term, p);
        if (v > bestv) { bestv = v; bt = p; }
    }

    if (nx == 0) {
        out[b] = bestv;
        float* path = out + BB + (size_t)b * (TT + 1);
        path[TT] = (float)bt;
        int cur = bt;
        for (int i = 1; i <= len; i++) {
            cur = bp[len - i][cur];
            path[TT - i] = (float)cur;
        }
        for (int idx = 0; idx < TT - len; idx++) path[idx] = (float)KK;
    }
}

// ---------------- launch ----------------
extern "C" void kernel_launch(void* const* d_in, const int* in_sizes, int n_in,
                              void* d_out, int out_size) {
    const int*   sent  = (const int*)d_in[0];
    const int*   lens  = (const int*)d_in[1];
    const float* emb   = (const float*)d_in[2];
    const float* Wf_ih = (const float*)d_in[3];
    const float* Wf_hh = (const float*)d_in[4];
    const float* bf_ih = (const float*)d_in[5];
    const float* bf_hh = (const float*)d_in[6];
    const float* Wb_ih = (const float*)d_in[7];
    const float* Wb_hh = (const float*)d_in[8];
    const float* bb_ih = (const float*)d_in[9];
    const float* bb_hh = (const float*)d_in[10];
    const float* Wout  = (const float*)d_in[11];
    const float* bout  = (const float*)d_in[12];
    const float* trans = (const float*)d_in[13];
    float* out = (float*)d_out;

    const int smem_pregemm = (128 * 68 + 64 * 258) * 4;          // ~98.5 KB
    const int smem_lstm    = 200704 + 32;                         // weights+h+part+4 mbarriers
    const int smem_feats   = (KK * 2 * HH + 2 * HH * BB) * 4;    // 208 KB
    cudaFuncSetAttribute(k_pregemm, cudaFuncAttributeMaxDynamicSharedMemorySize, smem_pregemm);
    cudaFuncSetAttribute(k_lstm,    cudaFuncAttributeMaxDynamicSharedMemorySize, smem_lstm);
    cudaFuncSetAttribute(k_feats,   cudaFuncAttributeMaxDynamicSharedMemorySize, smem_feats);

    k_init<<<1, 256>>>();
    k_nop<<<1, 32>>>();   // keep launch order identical (ncu window on k_lstm)

    k_pregemm<<<dim3(TT, G4 / 64, 2), 256, smem_pregemm>>>(sent, emb, Wf_ih, Wb_ih, bf_ih, bb_ih);

    k_lstm<<<NBLK, 256, smem_lstm>>>(Wf_hh, Wb_hh, bf_hh, bb_hh, lens);

    k_feats<<<TT / 4, 640, smem_feats>>>(Wout, bout);

    k_viterbi<<<BB, 32>>>(trans, lens, out);
}

// round 17
// speedup vs baseline: 1.3464x; 1.3464x over previous
#include <cuda_runtime.h>
#include <math.h>

#define BB 32
#define TT 256
#define EE 256
#define HH 512
#define G4 2048   // 4*HH
#define KK 20
#define START_TAG 18
#define END_TAG 19
#define NEGV (-10000.0f)
#define NBLK 128
#define WSTRIDE 264   // w-pair row stride in floats (1056 B, 16B-aligned!)

// ---------------- device-global scratch ----------------
__device__ float g_pre[(size_t)2 * TT * G4 * BB];              // [dir][t][gate][b]
__device__ __align__(16) float2 g_hp[2][2][256 * BB];          // [dir][buf][pair*BB+b]
__device__ float g_lo2[(size_t)2 * TT * HH * BB];              // [dir][t][j][b]
__device__ float g_feats[(size_t)BB * TT * KK];                // [b][t][k]
__device__ unsigned g_arrive[2][2];                            // [dir][k-half]

// ---------------- helpers ----------------
__device__ __forceinline__ unsigned smem_u32(const void* p) {
    unsigned a;
    asm("{ .reg .u64 t; cvta.to.shared.u64 t, %1; cvt.u32.u64 %0, t; }" : "=r"(a) : "l"(p));
    return a;
}
__device__ __forceinline__ void fma2(unsigned long long& acc, unsigned long long a, unsigned long long b) {
    asm("fma.rn.f32x2 %0, %1, %2, %0;" : "+l"(acc) : "l"(a), "l"(b));
}
__device__ __forceinline__ void lds_v2u64(unsigned addr, unsigned long long& a, unsigned long long& b) {
    asm("ld.shared.v2.u64 {%0,%1}, [%2];" : "=l"(a), "=l"(b) : "r"(addr));
}
__device__ __forceinline__ unsigned long long lds_u64(unsigned addr) {
    unsigned long long v;
    asm("ld.shared.u64 %0, [%1];" : "=l"(v) : "r"(addr));
    return v;
}
__device__ __forceinline__ float hsum2(unsigned long long a) {
    return __uint_as_float((unsigned)a) + __uint_as_float((unsigned)(a >> 32));
}
__device__ __forceinline__ void named_bar(int id) {
    asm volatile("bar.sync %0, 128;" :: "r"(id) : "memory");
}
__device__ __forceinline__ void mbar_wait(unsigned addr, unsigned parity) {
    unsigned done;
    do {
        asm volatile(
            "{ .reg .pred p;\n\t"
            "mbarrier.try_wait.parity.acquire.cta.shared::cta.b64 p, [%1], %2, 0x989680;\n\t"
            "selp.b32 %0, 1, 0, p; }"
            : "=r"(done) : "r"(addr), "r"(parity) : "memory");
    } while (!done);
}

// ---------------- init: reset barrier state (inside graph, every replay) ----------------
__global__ void k_init() {
    if (threadIdx.x < 4) ((unsigned*)g_arrive)[threadIdx.x] = 0u;
}

// no-op: launch-order shim so ncu's -s 5 window lands on k_lstm
__global__ void k_nop() {}

// ---------------- input-projection GEMM v2 (f32x2, 4x4 tile/thread) ----------------
// grid (TT, 16, 2), block 256.  Block covers 128 gate-rows x 32 b for one (t, dir).
// Thread (ty=tid>>3, tx=tid&7): rows 4ty..4ty+3, b 4tx..4tx+3 (16 outputs).
// Weights staged per k-half as pairs [ep][row][2] (stride 264 floats = 1056 B, 16B-
// aligned -> valid v2.u64); x staged [ep][b][2] (stride 68 floats = 272 B, aligned).
// Inner loop: 4 LDS.v2 (2 wavefronts w/ broadcast) + 16 FFMA2 per k-pair.
__global__ void __launch_bounds__(256) k_pregemm(
    const int* __restrict__ sent, const float* __restrict__ emb,
    const float* __restrict__ Wf, const float* __restrict__ Wb,
    const float* __restrict__ bf, const float* __restrict__ bb)
{
    extern __shared__ float sm[];
    float* xsf = sm;               // x pairs: [ep 0..127][b 0..31][2], stride 68
    float* wsf = sm + 8704;        // w pairs: [ep 0..63][row 0..127][2], stride WSTRIDE
    __shared__ int stok[BB];

    int t = blockIdx.x, gc = blockIdx.y, dir = blockIdx.z;
    int tid = threadIdx.x;
    if (tid < BB) stok[tid] = sent[tid * TT + t];
    __syncthreads();

    const float* W  = dir ? Wb : Wf;
    const float* bi = dir ? bb : bf;
    const int R0 = gc * 128;

    for (int i = tid; i < BB * EE; i += 256) {
        int b = i >> 8, e = i & 255;
        xsf[(e >> 1) * 68 + b * 2 + (e & 1)] = emb[(size_t)stok[b] * EE + e];
    }

    int ty = tid >> 3, tx = tid & 7;
    unsigned xb = smem_u32(xsf) + (unsigned)tx * 32u;
    unsigned wb = smem_u32(wsf) + (unsigned)ty * 32u;

    unsigned long long acc[4][4];
#pragma unroll
    for (int r = 0; r < 4; r++)
#pragma unroll
        for (int cb = 0; cb < 4; cb++) acc[r][cb] = 0ull;

#pragma unroll
    for (int kh2 = 0; kh2 < 2; kh2++) {
        __syncthreads();
        // stage this k-half's weights: 128 rows x 128 e (coalesced global reads)
        for (int i = tid; i < 128 * 128; i += 256) {
            int r = i >> 7, e = i & 127;
            wsf[(e >> 1) * WSTRIDE + r * 2 + (e & 1)] =
                W[(size_t)(R0 + r) * EE + kh2 * 128 + e];
        }
        __syncthreads();

        unsigned xoff = xb + (unsigned)(kh2 * 64) * 272u;
#pragma unroll 4
        for (int ep = 0; ep < 64; ep++) {
            unsigned long long w0, w1, w2, w3, x0, x1, x2, x3;
            unsigned wa = wb + (unsigned)ep * (WSTRIDE * 4u);
            lds_v2u64(wa,        w0, w1);    // rows 4ty, 4ty+1
            lds_v2u64(wa + 16u,  w2, w3);    // rows 4ty+2, 4ty+3
            unsigned xa = xoff + (unsigned)ep * 272u;
            lds_v2u64(xa,        x0, x1);    // b 4tx, 4tx+1
            lds_v2u64(xa + 16u,  x2, x3);    // b 4tx+2, 4tx+3
            fma2(acc[0][0], w0, x0); fma2(acc[0][1], w0, x1); fma2(acc[0][2], w0, x2); fma2(acc[0][3], w0, x3);
            fma2(acc[1][0], w1, x0); fma2(acc[1][1], w1, x1); fma2(acc[1][2], w1, x2); fma2(acc[1][3], w1, x3);
            fma2(acc[2][0], w2, x0); fma2(acc[2][1], w2, x1); fma2(acc[2][2], w2, x2); fma2(acc[2][3], w2, x3);
            fma2(acc[3][0], w3, x0); fma2(acc[3][1], w3, x1); fma2(acc[3][2], w3, x2); fma2(acc[3][3], w3, x3);
        }
    }

    size_t base = (((size_t)dir * TT + t) * G4 + R0) * BB;
#pragma unroll
    for (int r = 0; r < 4; r++) {
        int row = 4 * ty + r;
        float bv = bi[R0 + row];
        float4 st;
        st.x = hsum2(acc[r][0]) + bv;
        st.y = hsum2(acc[r][1]) + bv;
        st.z = hsum2(acc[r][2]) + bv;
        st.w = hsum2(acc[r][3]) + bv;
        *(float4*)&g_pre[base + (size_t)row * BB + 4 * tx] = st;
    }
}

// ---------------- persistent BiLSTM recurrence (R13 champion, unchanged) ----------------
// 128 blocks x 256 threads. warp w: dir=w>>2, p=(w>>1)&1 (j-pair), kh=w&1 (k-half).
// h exchange split per k-half: half hf produced by blocks jgrp in [64hf, 64hf+64).
// Two pollers per dir poll counter [dir][hf], then TMA 32KB + own mbarrier.
// MAC warp kh reads only half kh -> waits only mbar[dir][kh]. No mid-MAC waits.
__global__ void __launch_bounds__(256, 1) k_lstm(
    const float* __restrict__ Wfhh, const float* __restrict__ Wbhh,
    const float* __restrict__ bfhh, const float* __restrict__ bbhh,
    const int* __restrict__ lengths)
{
    extern __shared__ float sm[];
    // floats: [0,16384) interleaved weights; [16384,49152) h; [49152,50176) partials;
    // bytes 200704..200736: four mbarriers [dir][half]
    const int jgrp = (int)blockIdx.x;
    const int tid = threadIdx.x;
    const int w = tid >> 5, lane = tid & 31;
    const int dir = w >> 2, p = (w >> 1) & 1, kh = w & 1;
    const int q = w - dir * 4;                 // warp index within half, 0..3
    const int jown = jgrp * 4 + p * 2 + kh;
    const unsigned mbase = smem_u32(sm) + 200704u;

    // one-time: interleaved weight load
    for (int idx = tid; idx < 16384; idx += 256) {
        int ww = idx >> 11;
        int r = idx & 2047;
        int kq = r >> 4, c = r & 15;
        int jj = c >> 3, gate = (c >> 1) & 3, kk = c & 1;
        int d = ww >> 2, pp = (ww >> 1) & 1, kk2 = ww & 1;
        const float* W = d ? Wbhh : Wfhh;
        int jr = jgrp * 4 + pp * 2 + jj;
        int k = kk2 * 256 + kq * 2 + kk;
        sm[idx] = W[((size_t)(gate * HH + jr)) * HH + k];
    }
    for (int i = tid; i < 2 * HH * BB; i += 256) sm[16384 + i] = 0.0f;
    if (tid == 0) {
#pragma unroll
        for (int c = 0; c < 4; c++)
            asm volatile("mbarrier.init.shared.b64 [%0], 1;" :: "r"(mbase + (unsigned)c * 8u) : "memory");
    }
    __syncthreads();

    const float* bhh = dir ? bbhh : bfhh;
    float bg[4];
#pragma unroll
    for (int g = 0; g < 4; g++) bg[g] = bhh[g * HH + jown];
    const int mylen = lengths[lane];

    const unsigned smWb = smem_u32(sm) + (unsigned)w * 8192u;
    const unsigned smh  = smem_u32(sm) + 65536u + (unsigned)dir * 65536u + (unsigned)kh * 32768u + (unsigned)lane * 8u;
    const unsigned hdst = smem_u32(sm) + 65536u + (unsigned)dir * 65536u;
    const unsigned mb_own = mbase + (unsigned)(dir * 2 + kh) * 8u;
    float* part = sm + 49152;
    const int barid = 1 + dir;
    const bool is_poller = (q < 2) && (lane == 0);   // warps dir*4 (hf=0) and dir*4+1 (hf=1)

    // prefetch pre-gates for t=0
    float cz[4];
    int cpos = (dir && 0 < mylen) ? (mylen - 1) : 0;
    {
        size_t pb = (((size_t)dir * TT + cpos) * G4) * BB + lane;
#pragma unroll
        for (int g = 0; g < 4; g++) cz[g] = __ldcs(&g_pre[pb + (size_t)(g * HH + jown) * BB]);
    }

    float c = 0.0f;
    for (int t = 0; t < TT; t++) {
        // prefetch next-step pre-gates (independent of barrier / h)
        float nz[4] = {0.f, 0.f, 0.f, 0.f};
        int npos = 0;
        if (t + 1 < TT) {
            npos = t + 1;
            if (dir && (t + 1) < mylen) npos = mylen - 1 - (t + 1);
            size_t pb = (((size_t)dir * TT + npos) * G4) * BB + lane;
#pragma unroll
            for (int g = 0; g < 4; g++) nz[g] = __ldcs(&g_pre[pb + (size_t)(g * HH + jown) * BB]);
        }

        if (t) {
            // two pollers per dir: poll own half's counter, then TMA 32KB + complete_tx
            if (is_poller) {
                const int hf = q;    // 0 or 1
                unsigned need = 64u * (unsigned)t;
                unsigned r;
                for (;;) {
                    asm volatile("ld.acquire.gpu.global.u32 %0, [%1];"
                                 : "=r"(r) : "l"(&g_arrive[dir][hf]) : "memory");
                    if (r >= need) break;
                    __nanosleep(64);
                }
                unsigned mb = mbase + (unsigned)(dir * 2 + hf) * 8u;
                asm volatile("fence.proxy.async;" ::: "memory");
                asm volatile("mbarrier.arrive.expect_tx.shared.b64 _, [%0], %1;"
                             :: "r"(mb), "r"(32768u) : "memory");
                asm volatile("cp.async.bulk.shared::cluster.global.mbarrier::complete_tx::bytes [%0], [%1], %2, [%3];"
                             :: "r"(hdst + (unsigned)hf * 32768u),
                                "l"((const char*)&g_hp[dir][t & 1][0] + (size_t)hf * 32768),
                                "r"(32768u), "r"(mb)
                             : "memory");
            }
            // each MAC warp waits only the half it reads
            mbar_wait(mb_own, (unsigned)((t - 1) & 1));
        }

        // ---- MAC over this warp's k-half for both j's of the pair ----
        unsigned long long ai0 = 0, af0 = 0, ag0 = 0, ao0 = 0;
        unsigned long long ai1 = 0, af1 = 0, ag1 = 0, ao1 = 0;
#pragma unroll 4
        for (int kq = 0; kq < 128; kq++) {
            unsigned wa = smWb + (unsigned)kq * 64u;
            unsigned long long wi0, wf0, wg0, wo0, wi1, wf1, wg1, wo1;
            lds_v2u64(wa,       wi0, wf0);
            lds_v2u64(wa + 16u, wg0, wo0);
            lds_v2u64(wa + 32u, wi1, wf1);
            lds_v2u64(wa + 48u, wg1, wo1);
            unsigned long long h2 = lds_u64(smh + (unsigned)kq * 256u);
            fma2(ai0, wi0, h2); fma2(af0, wf0, h2); fma2(ag0, wg0, h2); fma2(ao0, wo0, h2);
            fma2(ai1, wi1, h2); fma2(af1, wf1, h2); fma2(ag1, wg1, h2); fma2(ao1, wo1, h2);
        }

        // partner partials: the j this warp does NOT own (jj = 1-kh)
        float po[4], pn[4];
        if (kh == 0) { pn[0] = hsum2(ai1); pn[1] = hsum2(af1); pn[2] = hsum2(ag1); pn[3] = hsum2(ao1);
                       po[0] = hsum2(ai0); po[1] = hsum2(af0); po[2] = hsum2(ag0); po[3] = hsum2(ao0); }
        else         { pn[0] = hsum2(ai0); pn[1] = hsum2(af0); pn[2] = hsum2(ag0); pn[3] = hsum2(ao0);
                       po[0] = hsum2(ai1); po[1] = hsum2(af1); po[2] = hsum2(ag1); po[3] = hsum2(ao1); }
#pragma unroll
        for (int g = 0; g < 4; g++) part[(w * 4 + g) * 32 + lane] = pn[g];
        named_bar(barid);

        float z[4];
#pragma unroll
        for (int g = 0; g < 4; g++)
            z[g] = cz[g] + bg[g] + po[g] + part[((w ^ 1) * 4 + g) * 32 + lane];

        float gi = 1.0f / (1.0f + expf(-z[0]));
        float gf = 1.0f / (1.0f + expf(-z[1]));
        float gg = 1.0f - 2.0f / (expf(2.0f * z[2]) + 1.0f);
        float go = 1.0f / (1.0f + expf(-z[3]));

        c = gf * c + gi * gg;
        float h = go * (1.0f - 2.0f / (expf(2.0f * c) + 1.0f));

        int pairIdx = jgrp * 2 + p;
        ((float*)&g_hp[dir][(t + 1) & 1][pairIdx * BB])[lane * 2 + kh] = h;
        g_lo2[(((size_t)dir * TT + cpos) * HH + jown) * BB + lane] = h;

        if (t + 1 < TT) {
            named_bar(barid);   // all 4 warps of this half stored h (and done reading smem h)
            if (tid == dir * 128) {
                asm volatile("red.release.gpu.global.add.u32 [%0], %1;"
                             :: "l"(&g_arrive[dir][jgrp >> 6]), "r"(1u) : "memory");
            }
        }
#pragma unroll
        for (int g = 0; g < 4; g++) cz[g] = nz[g];
        cpos = npos;
    }
}

// ---------------- feats: per-t GEMM, 4 timesteps per block (Wout staged once) ----------------
__global__ void __launch_bounds__(640) k_feats(
    const float* __restrict__ Wout, const float* __restrict__ bout)
{
    extern __shared__ float sm[];
    float* sW = sm;                 // [20][1024]
    float* sh = sm + 20480;         // [1024][32]
    __shared__ float sb[KK];
    int tid = threadIdx.x, warp = tid >> 5, lane = tid & 31;

    for (int i = tid * 4; i < KK * 2 * HH; i += 2560)
        *(float4*)&sW[i] = *(const float4*)&Wout[i];
    if (tid < KK) sb[tid] = bout[tid];

    for (int tt = 0; tt < 4; tt++) {
        int t = blockIdx.x * 4 + tt;
        for (int d = 0; d < 2; d++) {
            const float4* src = (const float4*)&g_lo2[(((size_t)d * TT + t) * HH) * BB];
            float4* dst = (float4*)&sh[d * HH * BB];
            for (int i = tid; i < HH * BB / 4; i += 640) dst[i] = src[i];
        }
        __syncthreads();

        float acc = 0.0f;
        const float* wrow = &sW[warp * 2 * HH];
#pragma unroll 8
        for (int jj = 0; jj < 2 * HH; jj += 4) {
            float4 wv = *(const float4*)&wrow[jj];
            acc = fmaf(wv.x, sh[(jj + 0) * BB + lane], acc);
            acc = fmaf(wv.y, sh[(jj + 1) * BB + lane], acc);
            acc = fmaf(wv.z, sh[(jj + 2) * BB + lane], acc);
            acc = fmaf(wv.w, sh[(jj + 3) * BB + lane], acc);
        }
        g_feats[((size_t)lane * TT + t) * KK + warp] = acc + sb[warp];
        __syncthreads();
    }
}

// ---------------- Viterbi forward + backtrace, one warp per batch ----------------
__global__ void k_viterbi(const float* __restrict__ trans,
                          const int* __restrict__ lengths,
                          float* __restrict__ out)
{
    __shared__ unsigned char bp[TT][KK];
    int b = blockIdx.x;
    int nx = threadIdx.x;
    int len = lengths[b];

    float tr[KK];
#pragma unroll
    for (int p = 0; p < KK; p++) tr[p] = (nx < KK) ? trans[nx * KK + p] : 0.0f;

    float fv = (nx == START_TAG) ? 0.0f : NEGV;
    for (int t = 0; t < len; t++) {
        float best = -INFINITY; int barg = 0;
#pragma unroll
        for (int p = 0; p < KK; p++) {
            float fvp = __shfl_sync(0xffffffffu, fv, p);
            float s = fvp + tr[p];
            if (s > best) { best = s; barg = p; }
        }
        if (nx < KK) {
            bp[t][nx] = (unsigned char)barg;
            fv = best + g_feats[((size_t)b * TT + t) * KK + nx];
        } else {
            fv = NEGV;
        }
        __syncwarp();
    }

    float term = (nx < KK) ? (fv + trans[END_TAG * KK + nx]) : -INFINITY;
    float bestv = -INFINITY; int bt = 0;
#pragma unroll
    for (int p = 0; p < KK; p++) {
        float v = __shfl_sync(0xffffffffu, term, p);
        if (v > bestv) { bestv = v; bt = p; }
    }

    if (nx == 0) {
        out[b] = bestv;
        float* path = out + BB + (size_t)b * (TT + 1);
        path[TT] = (float)bt;
        int cur = bt;
        for (int i = 1; i <= len; i++) {
            cur = bp[len - i][cur];
            path[TT - i] = (float)cur;
        }
        for (int idx = 0; idx < TT - len; idx++) path[idx] = (float)KK;
    }
}

// ---------------- launch ----------------
extern "C" void kernel_launch(void* const* d_in, const int* in_sizes, int n_in,
                              void* d_out, int out_size) {
    const int*   sent  = (const int*)d_in[0];
    const int*   lens  = (const int*)d_in[1];
    const float* emb   = (const float*)d_in[2];
    const float* Wf_ih = (const float*)d_in[3];
    const float* Wf_hh = (const float*)d_in[4];
    const float* bf_ih = (const float*)d_in[5];
    const float* bf_hh = (const float*)d_in[6];
    const float* Wb_ih = (const float*)d_in[7];
    const float* Wb_hh = (const float*)d_in[8];
    const float* bb_ih = (const float*)d_in[9];
    const float* bb_hh = (const float*)d_in[10];
    const float* Wout  = (const float*)d_in[11];
    const float* bout  = (const float*)d_in[12];
    const float* trans = (const float*)d_in[13];
    float* out = (float*)d_out;

    const int smem_pregemm = (8704 + 64 * WSTRIDE + 64) * 4;     // ~102 KB
    const int smem_lstm    = 200704 + 32;                         // weights+h+part+4 mbarriers
    const int smem_feats   = (KK * 2 * HH + 2 * HH * BB) * 4;    // 208 KB
    cudaFuncSetAttribute(k_pregemm, cudaFuncAttributeMaxDynamicSharedMemorySize, smem_pregemm);
    cudaFuncSetAttribute(k_lstm,    cudaFuncAttributeMaxDynamicSharedMemorySize, smem_lstm);
    cudaFuncSetAttribute(k_feats,   cudaFuncAttributeMaxDynamicSharedMemorySize, smem_feats);

    k_init<<<1, 32>>>();
    k_nop<<<1, 32>>>();   // keep launch order identical (ncu window on k_lstm)

    k_pregemm<<<dim3(TT, 16, 2), 256, smem_pregemm>>>(sent, emb, Wf_ih, Wb_ih, bf_ih, bb_ih);

    k_lstm<<<NBLK, 256, smem_lstm>>>(Wf_hh, Wb_hh, bf_hh, bb_hh, lens);

    k_feats<<<TT / 4, 640, smem_feats>>>(Wout, bout);

    k_viterbi<<<BB, 32>>>(trans, lens, out);
}